// round 1
// baseline (speedup 1.0000x reference)
#include <cuda_runtime.h>
#include <math.h>

#define K_CB 196560
#define EMB 24
#define TT 16

// ---------------- device scratch (static allocation only) ----------------
__device__ float g_res[12288];                 // residual [2][24][16][16]
__device__ float g_rdown[512 * EMB];           // downsampled tokens [N][24]
__device__ float g_zq[512 * EMB];              // quantized tokens (post-STE)
__device__ unsigned long long g_best[512];     // packed (orderable sim, ~idx)
__device__ float g_wd[10][16][16];             // down weights [s][inY][outy]
__device__ float g_wu[10][16][16];             // up   weights [s][iny][outY]

// ---------------- helpers ----------------
__device__ __forceinline__ unsigned int forder(float f) {
    unsigned int u = __float_as_uint(f);
    return (u & 0x80000000u) ? ~u : (u | 0x80000000u);
}

__device__ __forceinline__ unsigned long long ffma2(unsigned long long a,
                                                    unsigned long long b,
                                                    unsigned long long c) {
    unsigned long long d;
    asm("fma.rn.f32x2 %0, %1, %2, %3;" : "=l"(d) : "l"(a), "l"(b), "l"(c));
    return d;
}
__device__ __forceinline__ unsigned long long packf2(float lo, float hi) {
    unsigned long long r;
    asm("mov.b64 %0, {%1, %2};" : "=l"(r) : "f"(lo), "f"(hi));
    return r;
}
__device__ __forceinline__ float2 unpackf2(unsigned long long v) {
    float lo, hi;
    asm("mov.b64 {%0, %1}, %2;" : "=f"(lo), "=f"(hi) : "l"(v));
    return make_float2(lo, hi);
}

// Replicates jax.image.resize compute_weight_mat (triangle kernel,
// antialias=True, translation=0) for one output column o.
__device__ void compute_col(int in_size, int out_size, int o, float* wcol) {
    float inv_scale = (float)((double)in_size / (double)out_size);
    float kscale = fmaxf(inv_scale, 1.0f);
    float sample_f = ((float)o + 0.5f) * inv_scale - 0.5f;
    float total = 0.0f;
    for (int i = 0; i < in_size; ++i) {
        float x = fabsf(sample_f - (float)i) / kscale;
        float w = fmaxf(0.0f, 1.0f - x);
        wcol[i] = w;
        total += w;
    }
    bool ok = fabsf(total) > 1000.0f * 1.1920928955078125e-7f;
    float denom = (total != 0.0f) ? total : 1.0f;
    bool inr = (sample_f >= -0.5f) && (sample_f <= (float)in_size - 0.5f);
    for (int i = 0; i < in_size; ++i) {
        float w = ok ? (wcol[i] / denom) : 0.0f;
        wcol[i] = inr ? w : 0.0f;
    }
}

// ---------------- init: residual copy, zero z_hat, build weight mats ------
__global__ void init_kernel(const float* __restrict__ z, float* __restrict__ out) {
    int tid = threadIdx.x;
    for (int i = tid; i < 12288; i += blockDim.x) {
        g_res[i] = z[i];
        out[i] = 0.0f;
    }
    const int hs9[9] = {1, 2, 3, 4, 5, 6, 8, 10, 13};
    // 52 down-columns + 9*16 up-columns = 196 tasks
    for (int task = tid; task < 52 + 144; task += blockDim.x) {
        float wcol[16];
        if (task < 52) {
            int rem = task, s = 0;
            while (rem >= hs9[s]) { rem -= hs9[s]; s++; }
            compute_col(16, hs9[s], rem, wcol);
            for (int i = 0; i < 16; i++) g_wd[s][i][rem] = wcol[i];
        } else {
            int r = task - 52;
            int s = r / 16, o = r % 16;
            compute_col(hs9[s], 16, o, wcol);
            for (int i = 0; i < 16; i++) g_wu[s][i][o] = (i < hs9[s]) ? wcol[i] : 0.0f;
        }
    }
}

// ---------------- downsample residual -> tokens (separable H then W) ------
__global__ void downsample_kernel(int s, int h, int N) {
    __shared__ float tile[16][16];
    __shared__ float tmp[16][16];
    int blk = blockIdx.x;        // b*24 + d
    int tid = threadIdx.x;
    tile[tid >> 4][tid & 15] = g_res[blk * 256 + tid];
    if (blk == 0) {
        for (int n = tid; n < N; n += 256) g_best[n] = 0ull;
    }
    __syncthreads();
    int b = blk / 24, d = blk % 24;
    if (h == 16) {  // jax resize skips equal dims -> identity
        g_rdown[(b * 256 + tid) * EMB + d] = tile[tid >> 4][tid & 15];
        return;
    }
    if (tid < h * 16) {
        int y = tid / 16, X = tid % 16;
        float acc = 0.0f;
        for (int Y = 0; Y < 16; Y++) acc += g_wd[s][Y][y] * tile[Y][X];
        tmp[y][X] = acc;
    }
    __syncthreads();
    if (tid < h * h) {
        int y = tid / h, x = tid % h;
        float acc = 0.0f;
        for (int X = 0; X < 16; X++) acc += g_wd[s][X][x] * tmp[y][X];
        g_rdown[(b * h * h + tid) * EMB + d] = acc;
    }
}

// ---------------- the heavy scan: argmax over 196560 codewords ------------
__global__ void __launch_bounds__(256) scan_kernel(const float* __restrict__ cb,
                                                   int N, int rows_per_block) {
    __shared__ __align__(16) float tok[TT][24];
    __shared__ unsigned long long wred[8][TT];
    int tid = threadIdx.x;
    int token0 = blockIdx.y * TT;
    for (int i = tid; i < TT * 24; i += 256) {
        int t = i / 24, d = i % 24;
        int tk = token0 + t;
        tok[t][d] = (tk < N) ? g_rdown[tk * EMB + d] : 0.0f;
    }
    __syncthreads();

    float bestv[TT];
    int besti[TT];
#pragma unroll
    for (int t = 0; t < TT; t++) { bestv[t] = -3.4e38f; besti[t] = 0; }

    int rbeg = blockIdx.x * rows_per_block;
    int rend = min(K_CB, rbeg + rows_per_block);
    const float4* __restrict__ cbv = (const float4*)cb;

    for (int r = rbeg + tid; r < rend; r += 256) {
        float4 c0 = __ldg(&cbv[r * 6 + 0]);
        float4 c1 = __ldg(&cbv[r * 6 + 1]);
        float4 c2 = __ldg(&cbv[r * 6 + 2]);
        float4 c3 = __ldg(&cbv[r * 6 + 3]);
        float4 c4 = __ldg(&cbv[r * 6 + 4]);
        float4 c5 = __ldg(&cbv[r * 6 + 5]);
        unsigned long long cp[12];
        cp[0]  = packf2(c0.x, c0.y); cp[1]  = packf2(c0.z, c0.w);
        cp[2]  = packf2(c1.x, c1.y); cp[3]  = packf2(c1.z, c1.w);
        cp[4]  = packf2(c2.x, c2.y); cp[5]  = packf2(c2.z, c2.w);
        cp[6]  = packf2(c3.x, c3.y); cp[7]  = packf2(c3.z, c3.w);
        cp[8]  = packf2(c4.x, c4.y); cp[9]  = packf2(c4.z, c4.w);
        cp[10] = packf2(c5.x, c5.y); cp[11] = packf2(c5.z, c5.w);
#pragma unroll
        for (int t = 0; t < TT; t++) {
            const ulonglong2* tz = (const ulonglong2*)tok[t];
            ulonglong2 z0 = tz[0], z1 = tz[1], z2 = tz[2];
            unsigned long long acc = ffma2(cp[0], z0.x, 0ull);
            acc = ffma2(cp[1], z0.y, acc);
            acc = ffma2(cp[2], z1.x, acc);
            acc = ffma2(cp[3], z1.y, acc);
            acc = ffma2(cp[4], z2.x, acc);
            acc = ffma2(cp[5], z2.y, acc);
            ulonglong2 z3 = tz[3], z4 = tz[4], z5 = tz[5];
            acc = ffma2(cp[6], z3.x, acc);
            acc = ffma2(cp[7], z3.y, acc);
            acc = ffma2(cp[8], z4.x, acc);
            acc = ffma2(cp[9], z4.y, acc);
            acc = ffma2(cp[10], z5.x, acc);
            acc = ffma2(cp[11], z5.y, acc);
            float2 s2 = unpackf2(acc);
            float sim = s2.x + s2.y;
            if (sim > bestv[t]) { bestv[t] = sim; besti[t] = r; }
        }
    }

    unsigned long long p[TT];
#pragma unroll
    for (int t = 0; t < TT; t++)
        p[t] = ((unsigned long long)forder(bestv[t]) << 32) |
               (unsigned long long)((unsigned)~besti[t]);
#pragma unroll
    for (int t = 0; t < TT; t++) {
#pragma unroll
        for (int off = 16; off; off >>= 1) {
            unsigned long long o = __shfl_down_sync(0xFFFFFFFFu, p[t], off);
            if (o > p[t]) p[t] = o;
        }
    }
    int warp = tid >> 5, lane = tid & 31;
    if (lane == 0) {
#pragma unroll
        for (int t = 0; t < TT; t++) wred[warp][t] = p[t];
    }
    __syncthreads();
    if (tid < TT) {
        unsigned long long m = wred[0][tid];
#pragma unroll
        for (int w = 1; w < 8; w++) {
            unsigned long long v = wred[w][tid];
            if (v > m) m = v;
        }
        if (token0 + tid < N) atomicMax(&g_best[token0 + tid], m);
    }
}

// ---------------- gather + renorm + STE, emit index ----------------------
__global__ void finalize_kernel(const float* __restrict__ cb, int N,
                                float* __restrict__ out, int idx_off) {
    int n = blockIdx.x * blockDim.x + threadIdx.x;
    if (n >= N) return;
    unsigned long long p = g_best[n];
    unsigned row = ~((unsigned)(p & 0xFFFFFFFFull));
    out[idx_off + n] = (float)row;
    const float* c = cb + (size_t)row * EMB;
    float ss = 0.0f;
    for (int d = 0; d < EMB; d++) { float v = c[d]; ss += v * v; }
    float nrm = sqrtf(ss);
    for (int d = 0; d < EMB; d++) {
        float q = c[d] / nrm;
        float zf = g_rdown[n * EMB + d];
        g_zq[n * EMB + d] = zf + (q - zf);   // STE forward rounding, ulp-exact
    }
}

// ---------------- upsample + accumulate z_hat, subtract residual ---------
__global__ void upsample_kernel(int s, int h, float* __restrict__ zhat) {
    __shared__ float zt[16][16];
    __shared__ float tmp[16][16];
    int blk = blockIdx.x, tid = threadIdx.x;
    int b = blk / 24, d = blk % 24;
    if (tid < h * h) zt[tid / h][tid % h] = g_zq[(b * h * h + tid) * EMB + d];
    __syncthreads();
    float up;
    if (h == 16) {
        up = zt[tid >> 4][tid & 15];
    } else {
        if (tid < 16 * h) {
            int Y = tid / h, x = tid % h;
            float acc = 0.0f;
            for (int y = 0; y < h; y++) acc += g_wu[s][y][Y] * zt[y][x];
            tmp[Y][x] = acc;
        }
        __syncthreads();
        int Y = tid >> 4, X = tid & 15;
        float acc = 0.0f;
        for (int x = 0; x < h; x++) acc += g_wu[s][x][X] * tmp[Y][x];
        up = acc;
    }
    int g = blk * 256 + tid;
    zhat[g] += up;
    g_res[g] -= up;
}

// ---------------- launch ---------------------------------------------------
extern "C" void kernel_launch(void* const* d_in, const int* in_sizes, int n_in,
                              void* d_out, int out_size) {
    const float* z;
    const float* cb;
    if (in_sizes[0] == 12288) {
        z = (const float*)d_in[0];
        cb = (const float*)d_in[1];
    } else {
        z = (const float*)d_in[1];
        cb = (const float*)d_in[0];
    }
    float* out = (float*)d_out;

    init_kernel<<<1, 256>>>(z, out);

    static const int hs[10] = {1, 2, 3, 4, 5, 6, 8, 10, 13, 16};
    int off = 12288;
    for (int s = 0; s < 10; s++) {
        int h = hs[s];
        int N = 2 * h * h;
        downsample_kernel<<<48, 256>>>(s, h, N);
        int tiles = (N + TT - 1) / TT;
        int gx = 2048 / tiles;
        if (gx > 768) gx = 768;
        if (gx < 1) gx = 1;
        int rpb = (K_CB + gx - 1) / gx;
        scan_kernel<<<dim3(gx, tiles), 256>>>(cb, N, rpb);
        finalize_kernel<<<(N + 127) / 128, 128>>>(cb, N, out, off);
        upsample_kernel<<<48, 256>>>(s, h, out);
        off += N;
    }
}

// round 2
// speedup vs baseline: 1.0023x; 1.0023x over previous
#include <cuda_runtime.h>
#include <math.h>

#define K_CB 196560
#define EMB 24
#define TT 16

// ---------------- device scratch (static allocation only) ----------------
__device__ float g_res[12288];                 // residual [2][24][16][16]
__device__ float g_rdown[512 * EMB];           // downsampled tokens [N][24]
__device__ float g_zq[512 * EMB];              // quantized tokens (post-STE)
__device__ unsigned long long g_best[512];     // packed (orderable sim, ~idx)
__device__ float g_wd[10][16][16];             // down weights [s][inY][outy]
__device__ float g_wu[10][16][16];             // up   weights [s][iny][outY]

// ---------------- helpers ----------------
__device__ __forceinline__ unsigned int forder(float f) {
    unsigned int u = __float_as_uint(f);
    return (u & 0x80000000u) ? ~u : (u | 0x80000000u);
}

__device__ __forceinline__ unsigned long long ffma2(unsigned long long a,
                                                    unsigned long long b,
                                                    unsigned long long c) {
    unsigned long long d;
    asm("fma.rn.f32x2 %0, %1, %2, %3;" : "=l"(d) : "l"(a), "l"(b), "l"(c));
    return d;
}
__device__ __forceinline__ unsigned long long packf2(float lo, float hi) {
    unsigned long long r;
    asm("mov.b64 %0, {%1, %2};" : "=l"(r) : "f"(lo), "f"(hi));
    return r;
}
__device__ __forceinline__ float2 unpackf2(unsigned long long v) {
    float lo, hi;
    asm("mov.b64 {%0, %1}, %2;" : "=f"(lo), "=f"(hi) : "l"(v));
    return make_float2(lo, hi);
}

// Replicates jax.image.resize compute_weight_mat (triangle kernel,
// antialias=True, translation=0) for one output column o.
__device__ void compute_col(int in_size, int out_size, int o, float* wcol) {
    float inv_scale = (float)((double)in_size / (double)out_size);
    float kscale = fmaxf(inv_scale, 1.0f);
    float sample_f = ((float)o + 0.5f) * inv_scale - 0.5f;
    float total = 0.0f;
    for (int i = 0; i < in_size; ++i) {
        float x = fabsf(sample_f - (float)i) / kscale;
        float w = fmaxf(0.0f, 1.0f - x);
        wcol[i] = w;
        total += w;
    }
    bool ok = fabsf(total) > 1000.0f * 1.1920928955078125e-7f;
    float denom = (total != 0.0f) ? total : 1.0f;
    bool inr = (sample_f >= -0.5f) && (sample_f <= (float)in_size - 0.5f);
    for (int i = 0; i < in_size; ++i) {
        float w = ok ? (wcol[i] / denom) : 0.0f;
        wcol[i] = inr ? w : 0.0f;
    }
}

// ---------------- init: residual copy, zero z_hat, build weight mats ------
__global__ void init_kernel(const float* __restrict__ z, float* __restrict__ out) {
    int tid = threadIdx.x;
    for (int i = tid; i < 12288; i += blockDim.x) {
        g_res[i] = z[i];
        out[i] = 0.0f;
    }
    const int hs9[9] = {1, 2, 3, 4, 5, 6, 8, 10, 13};
    // 52 down-columns + 9*16 up-columns = 196 tasks
    for (int task = tid; task < 52 + 144; task += blockDim.x) {
        float wcol[16];
        if (task < 52) {
            int rem = task, s = 0;
            while (rem >= hs9[s]) { rem -= hs9[s]; s++; }
            compute_col(16, hs9[s], rem, wcol);
            for (int i = 0; i < 16; i++) g_wd[s][i][rem] = wcol[i];
        } else {
            int r = task - 52;
            int s = r / 16, o = r % 16;
            compute_col(hs9[s], 16, o, wcol);
            for (int i = 0; i < 16; i++) g_wu[s][i][o] = (i < hs9[s]) ? wcol[i] : 0.0f;
        }
    }
}

// ---------------- downsample residual -> tokens (separable H then W) ------
__global__ void downsample_kernel(int s, int h, int N) {
    __shared__ float tile[16][16];
    __shared__ float tmp[16][16];
    int blk = blockIdx.x;        // b*24 + d
    int tid = threadIdx.x;
    tile[tid >> 4][tid & 15] = g_res[blk * 256 + tid];
    if (blk == 0) {
        for (int n = tid; n < N; n += 256) g_best[n] = 0ull;
    }
    __syncthreads();
    int b = blk / 24, d = blk % 24;
    if (h == 16) {  // jax resize skips equal dims -> identity
        g_rdown[(b * 256 + tid) * EMB + d] = tile[tid >> 4][tid & 15];
        return;
    }
    if (tid < h * 16) {
        int y = tid / 16, X = tid % 16;
        float acc = 0.0f;
        for (int Y = 0; Y < 16; Y++) acc += g_wd[s][Y][y] * tile[Y][X];
        tmp[y][X] = acc;
    }
    __syncthreads();
    if (tid < h * h) {
        int y = tid / h, x = tid % h;
        float acc = 0.0f;
        for (int X = 0; X < 16; X++) acc += g_wd[s][X][x] * tmp[y][X];
        g_rdown[(b * h * h + tid) * EMB + d] = acc;
    }
}

// ---------------- the heavy scan: argmax over 196560 codewords ------------
__global__ void __launch_bounds__(256) scan_kernel(const float* __restrict__ cb,
                                                   int N, int rows_per_block) {
    __shared__ __align__(16) float tok[TT][24];
    __shared__ unsigned long long wred[8][TT];
    int tid = threadIdx.x;
    int token0 = blockIdx.y * TT;
    for (int i = tid; i < TT * 24; i += 256) {
        int t = i / 24, d = i % 24;
        int tk = token0 + t;
        tok[t][d] = (tk < N) ? g_rdown[tk * EMB + d] : 0.0f;
    }
    __syncthreads();

    float bestv[TT];
    int besti[TT];
#pragma unroll
    for (int t = 0; t < TT; t++) { bestv[t] = -3.4e38f; besti[t] = 0; }

    int rbeg = blockIdx.x * rows_per_block;
    int rend = min(K_CB, rbeg + rows_per_block);
    const float4* __restrict__ cbv = (const float4*)cb;

    for (int r = rbeg + tid; r < rend; r += 256) {
        float4 c0 = __ldg(&cbv[r * 6 + 0]);
        float4 c1 = __ldg(&cbv[r * 6 + 1]);
        float4 c2 = __ldg(&cbv[r * 6 + 2]);
        float4 c3 = __ldg(&cbv[r * 6 + 3]);
        float4 c4 = __ldg(&cbv[r * 6 + 4]);
        float4 c5 = __ldg(&cbv[r * 6 + 5]);
        unsigned long long cp[12];
        cp[0]  = packf2(c0.x, c0.y); cp[1]  = packf2(c0.z, c0.w);
        cp[2]  = packf2(c1.x, c1.y); cp[3]  = packf2(c1.z, c1.w);
        cp[4]  = packf2(c2.x, c2.y); cp[5]  = packf2(c2.z, c2.w);
        cp[6]  = packf2(c3.x, c3.y); cp[7]  = packf2(c3.z, c3.w);
        cp[8]  = packf2(c4.x, c4.y); cp[9]  = packf2(c4.z, c4.w);
        cp[10] = packf2(c5.x, c5.y); cp[11] = packf2(c5.z, c5.w);
#pragma unroll
        for (int t = 0; t < TT; t++) {
            const ulonglong2* tz = (const ulonglong2*)tok[t];
            ulonglong2 z0 = tz[0], z1 = tz[1], z2 = tz[2];
            unsigned long long acc = ffma2(cp[0], z0.x, 0ull);
            acc = ffma2(cp[1], z0.y, acc);
            acc = ffma2(cp[2], z1.x, acc);
            acc = ffma2(cp[3], z1.y, acc);
            acc = ffma2(cp[4], z2.x, acc);
            acc = ffma2(cp[5], z2.y, acc);
            ulonglong2 z3 = tz[3], z4 = tz[4], z5 = tz[5];
            acc = ffma2(cp[6], z3.x, acc);
            acc = ffma2(cp[7], z3.y, acc);
            acc = ffma2(cp[8], z4.x, acc);
            acc = ffma2(cp[9], z4.y, acc);
            acc = ffma2(cp[10], z5.x, acc);
            acc = ffma2(cp[11], z5.y, acc);
            float2 s2 = unpackf2(acc);
            float sim = s2.x + s2.y;
            if (sim > bestv[t]) { bestv[t] = sim; besti[t] = r; }
        }
    }

    unsigned long long p[TT];
#pragma unroll
    for (int t = 0; t < TT; t++)
        p[t] = ((unsigned long long)forder(bestv[t]) << 32) |
               (unsigned long long)((unsigned)~besti[t]);
#pragma unroll
    for (int t = 0; t < TT; t++) {
#pragma unroll
        for (int off = 16; off; off >>= 1) {
            unsigned long long o = __shfl_down_sync(0xFFFFFFFFu, p[t], off);
            if (o > p[t]) p[t] = o;
        }
    }
    int warp = tid >> 5, lane = tid & 31;
    if (lane == 0) {
#pragma unroll
        for (int t = 0; t < TT; t++) wred[warp][t] = p[t];
    }
    __syncthreads();
    if (tid < TT) {
        unsigned long long m = wred[0][tid];
#pragma unroll
        for (int w = 1; w < 8; w++) {
            unsigned long long v = wred[w][tid];
            if (v > m) m = v;
        }
        if (token0 + tid < N) atomicMax(&g_best[token0 + tid], m);
    }
}

// ---------------- gather + renorm + STE, emit index ----------------------
__global__ void finalize_kernel(const float* __restrict__ cb, int N,
                                float* __restrict__ out, int idx_off) {
    int n = blockIdx.x * blockDim.x + threadIdx.x;
    if (n >= N) return;
    unsigned long long p = g_best[n];
    unsigned row = ~((unsigned)(p & 0xFFFFFFFFull));
    out[idx_off + n] = (float)row;
    const float* c = cb + (size_t)row * EMB;
    float ss = 0.0f;
    for (int d = 0; d < EMB; d++) { float v = c[d]; ss += v * v; }
    float nrm = sqrtf(ss);
    for (int d = 0; d < EMB; d++) {
        float q = c[d] / nrm;
        float zf = g_rdown[n * EMB + d];
        g_zq[n * EMB + d] = zf + (q - zf);   // STE forward rounding, ulp-exact
    }
}

// ---------------- upsample + accumulate z_hat, subtract residual ---------
__global__ void upsample_kernel(int s, int h, float* __restrict__ zhat) {
    __shared__ float zt[16][16];
    __shared__ float tmp[16][16];
    int blk = blockIdx.x, tid = threadIdx.x;
    int b = blk / 24, d = blk % 24;
    if (tid < h * h) zt[tid / h][tid % h] = g_zq[(b * h * h + tid) * EMB + d];
    __syncthreads();
    float up;
    if (h == 16) {
        up = zt[tid >> 4][tid & 15];
    } else {
        if (tid < 16 * h) {
            int Y = tid / h, x = tid % h;
            float acc = 0.0f;
            for (int y = 0; y < h; y++) acc += g_wu[s][y][Y] * zt[y][x];
            tmp[Y][x] = acc;
        }
        __syncthreads();
        int Y = tid >> 4, X = tid & 15;
        float acc = 0.0f;
        for (int x = 0; x < h; x++) acc += g_wu[s][x][X] * tmp[Y][x];
        up = acc;
    }
    int g = blk * 256 + tid;
    zhat[g] += up;
    g_res[g] -= up;
}

// ---------------- launch ---------------------------------------------------
extern "C" void kernel_launch(void* const* d_in, const int* in_sizes, int n_in,
                              void* d_out, int out_size) {
    const float* z;
    const float* cb;
    if (in_sizes[0] == 12288) {
        z = (const float*)d_in[0];
        cb = (const float*)d_in[1];
    } else {
        z = (const float*)d_in[1];
        cb = (const float*)d_in[0];
    }
    float* out = (float*)d_out;

    init_kernel<<<1, 256>>>(z, out);

    static const int hs[10] = {1, 2, 3, 4, 5, 6, 8, 10, 13, 16};
    int off = 12288;
    for (int s = 0; s < 10; s++) {
        int h = hs[s];
        int N = 2 * h * h;
        downsample_kernel<<<48, 256>>>(s, h, N);
        int tiles = (N + TT - 1) / TT;
        int gx = 2048 / tiles;
        if (gx > 768) gx = 768;
        if (gx < 1) gx = 1;
        int rpb = (K_CB + gx - 1) / gx;
        scan_kernel<<<dim3(gx, tiles), 256>>>(cb, N, rpb);
        finalize_kernel<<<(N + 127) / 128, 128>>>(cb, N, out, off);
        upsample_kernel<<<48, 256>>>(s, h, out);
        off += N;
    }
}